// round 1
// baseline (speedup 1.0000x reference)
#include <cuda_runtime.h>

#define NMAX 50000
#define EMAX 800000
#define TOTE (NMAX + EMAX)

// ---- scratch (device globals: no allocation allowed) ----
__device__ int g_cnt[NMAX];
__device__ int g_rowptr[NMAX + 1];
__device__ int g_cur[NMAX];
__device__ int g_adj[TOTE];
__device__ __align__(16) float g_hl0[256];     // layer-0 linear output, 2 rows x 128
__device__ float g_beta0[4];                   // layer-0 logits, 2 types x 2 heads
__device__ __align__(16) float g_hmid[(size_t)NMAX * 64];   // layer-0 output (post relu)
__device__ __align__(16) float g_hlin[(size_t)NMAX * 128];  // layer-1 linear output
__device__ __align__(16) float g_beta[(size_t)NMAX * 2];    // layer-1 logits per node/head

__device__ __forceinline__ float leaky(float v) { return v > 0.f ? v : 0.2f * v; }

// ======================= CSR build =======================
__global__ void k_init(int n) {
    int i = blockIdx.x * blockDim.x + threadIdx.x;
    if (i < n) g_cnt[i] = 1;  // self-loop
}

__global__ void k_hist(const int* __restrict__ ei, int E) {
    int e = blockIdx.x * blockDim.x + threadIdx.x;
    if (e < E) atomicAdd(&g_cnt[ei[e]], 1);
}

__global__ void k_scan(int n) {
    __shared__ int part[1024];
    int t = threadIdx.x;
    int chunk = (n + 1023) >> 10;
    int beg = t * chunk;
    int end = min(beg + chunk, n);
    int s = 0;
    for (int i = beg; i < end; i++) s += g_cnt[i];
    part[t] = s;
    __syncthreads();
    for (int off = 1; off < 1024; off <<= 1) {
        int tmp = (t >= off) ? part[t - off] : 0;
        __syncthreads();
        part[t] += tmp;
        __syncthreads();
    }
    int run = part[t] - s;  // exclusive prefix of this chunk
    for (int i = beg; i < end; i++) { g_rowptr[i] = run; run += g_cnt[i]; }
    if (t == 0) g_rowptr[n] = part[1023];
}

__global__ void k_scatter_init(int n) {
    int i = blockIdx.x * blockDim.x + threadIdx.x;
    if (i < n) {
        int p = g_rowptr[i];
        g_adj[p] = i;        // self-loop first
        g_cur[i] = p + 1;
    }
}

__global__ void k_scatter(const int* __restrict__ ei, int E) {
    int e = blockIdx.x * blockDim.x + threadIdx.x;
    if (e < E) {
        int s = ei[e];
        int d = ei[E + e];
        int p = atomicAdd(&g_cur[s], 1);
        g_adj[p] = d;
    }
}

// ======================= layer 0 =======================
// Only 2 distinct input rows -> compute the 2x128 linear output + 2x2 logits.
__global__ void k_l0_prep(const float* __restrict__ emb, const float* __restrict__ Ws,
                          const float* __restrict__ bs, const float* __restrict__ atts) {
    __shared__ float sh[256];
    int t = threadIdx.x;
    int row = t >> 7, col = t & 127;
    float acc = bs[col];
#pragma unroll
    for (int k = 0; k < 64; k++) acc += emb[row * 64 + k] * Ws[k * 128 + col];
    g_hl0[t] = acc;
    sh[t] = acc;
    __syncthreads();
    if (t < 4) {
        int r = t >> 1, h = t & 1;
        float s = 0.f;
        for (int d = 0; d < 64; d++) s += sh[r * 128 + h * 64 + d] * atts[h * 64 + d];
        g_beta0[r * 2 + h] = leaky(s);
    }
}

// Layer-0 aggregation: per node we only need the count of type-0 neighbors.
__global__ __launch_bounds__(256) void k_l0_aggr(const int* __restrict__ x,
                                                 const float* __restrict__ biases, int n_nodes) {
    int gw = (blockIdx.x * blockDim.x + threadIdx.x) >> 5;
    int lane = threadIdx.x & 31;
    if (gw >= n_nodes) return;
    int n = gw;
    int s = g_rowptr[n], e = g_rowptr[n + 1];
    int c0 = 0;
    for (int i = s + lane; i < e; i += 32) c0 += (x[g_adj[i]] == 0);
#pragma unroll
    for (int o = 16; o; o >>= 1) c0 += __shfl_xor_sync(0xffffffffu, c0, o);

    int head = lane >> 4;
    int dl = (lane & 15) << 2;    // d within head
    int c = head * 64 + dl;       // column in 128-wide layout
    float4 v0 = *(const float4*)(g_hl0 + c);
    float4 v1 = *(const float4*)(g_hl0 + 128 + c);
    float b0 = g_beta0[head], b1 = g_beta0[2 + head];
    float m = fmaxf(b0, b1);
    float w0 = __expf(b0 - m), w1 = __expf(b1 - m);
    float deg = (float)(e - s);
    float c0f = (float)c0, c1f = deg - c0f;
    float denom = c0f * w0 + c1f * w1 + 1e-16f;
    float A = c0f * w0 / denom, B = c1f * w1 / denom;
    int t = x[n];
    float4 vt = t ? v1 : v0;
    float4 r;
    r.x = deg * vt.x + A * v0.x + B * v1.x;
    r.y = deg * vt.y + A * v0.y + B * v1.y;
    r.z = deg * vt.z + A * v0.z + B * v1.z;
    r.w = deg * vt.w + A * v0.w + B * v1.w;
    float4 q;
    q.x = __shfl_xor_sync(0xffffffffu, r.x, 16);
    q.y = __shfl_xor_sync(0xffffffffu, r.y, 16);
    q.z = __shfl_xor_sync(0xffffffffu, r.z, 16);
    q.w = __shfl_xor_sync(0xffffffffu, r.w, 16);
    if (lane < 16) {
        float4 o4;
        o4.x = fmaxf(0.f, 0.5f * (r.x + q.x) + biases[dl + 0]);
        o4.y = fmaxf(0.f, 0.5f * (r.y + q.y) + biases[dl + 1]);
        o4.z = fmaxf(0.f, 0.5f * (r.z + q.z) + biases[dl + 2]);
        o4.w = fmaxf(0.f, 0.5f * (r.w + q.w) + biases[dl + 3]);
        *(float4*)(g_hmid + (size_t)n * 64 + dl) = o4;
    }
}

// ======================= layer 1 =======================
// Warp-per-node GEMM: [N,64] @ W1[64,128] + b1, plus per-node attention logits.
__global__ __launch_bounds__(256) void k_l1_gemm(const float* __restrict__ Ws,
                                                 const float* __restrict__ bs,
                                                 const float* __restrict__ atts, int n_nodes) {
    __shared__ float4 sW[64 * 32];  // sW[k*32+l] = {W[k][l], W[k][l+32], W[k][l+64], W[k][l+96]}
    __shared__ float sx[8][64];
    const float* W1 = Ws + 64 * 128;
    const float* b1 = bs + 128;
    const float* att1 = atts + 128;
    for (int idx = threadIdx.x; idx < 2048; idx += 256) {
        int k = idx >> 5, l = idx & 31;
        const float* wr = W1 + k * 128 + l;
        sW[idx] = make_float4(wr[0], wr[32], wr[64], wr[96]);
    }
    __syncthreads();
    int warp = threadIdx.x >> 5, lane = threadIdx.x & 31;
    int n = blockIdx.x * 8 + warp;
    if (n >= n_nodes) return;
    const float* xr = g_hmid + (size_t)n * 64;
    sx[warp][lane] = xr[lane];
    sx[warp][lane + 32] = xr[lane + 32];
    __syncwarp();
    float4 acc = make_float4(b1[lane], b1[lane + 32], b1[lane + 64], b1[lane + 96]);
#pragma unroll
    for (int k = 0; k < 64; k++) {
        float xk = sx[warp][k];
        float4 w = sW[(k << 5) + lane];
        acc.x = fmaf(xk, w.x, acc.x);
        acc.y = fmaf(xk, w.y, acc.y);
        acc.z = fmaf(xk, w.z, acc.z);
        acc.w = fmaf(xk, w.w, acc.w);
    }
    float* o = g_hlin + (size_t)n * 128;
    o[lane] = acc.x;
    o[lane + 32] = acc.y;
    o[lane + 64] = acc.z;
    o[lane + 96] = acc.w;
    // attention logits: head0 = cols [0,64), head1 = cols [64,128)
    float p0 = acc.x * att1[lane] + acc.y * att1[lane + 32];
    float p1 = acc.z * att1[64 + lane] + acc.w * att1[96 + lane];
#pragma unroll
    for (int off = 16; off; off >>= 1) {
        p0 += __shfl_xor_sync(0xffffffffu, p0, off);
        p1 += __shfl_xor_sync(0xffffffffu, p1, off);
    }
    if (lane == 0) {
        g_beta[2 * n] = leaky(p0);
        g_beta[2 * n + 1] = leaky(p1);
    }
}

// Layer-1 aggregation: warp per node, two passes over the adjacency (max, then
// weighted sum). h_lin is 25.6MB -> L2 resident; each edge costs one coalesced
// 512B gather. Epilogue: normalize, add deg*self, mean heads, bias, write out.
__global__ __launch_bounds__(256) void k_l1_aggr(const float* __restrict__ biases,
                                                 float* __restrict__ out, int n_nodes) {
    int gw = (blockIdx.x * blockDim.x + threadIdx.x) >> 5;
    int lane = threadIdx.x & 31;
    if (gw >= n_nodes) return;
    int n = gw;
    int s = g_rowptr[n], e = g_rowptr[n + 1];
    // pass 1: per-head max of beta over neighbors
    float m0 = -3e38f, m1 = -3e38f;
    for (int i = s + lane; i < e; i += 32) {
        int d = g_adj[i];
        float2 b = *(const float2*)(g_beta + 2 * d);
        m0 = fmaxf(m0, b.x);
        m1 = fmaxf(m1, b.y);
    }
#pragma unroll
    for (int o = 16; o; o >>= 1) {
        m0 = fmaxf(m0, __shfl_xor_sync(0xffffffffu, m0, o));
        m1 = fmaxf(m1, __shfl_xor_sync(0xffffffffu, m1, o));
    }
    int head = lane >> 4;            // lane l covers columns [4l, 4l+4)
    float mh = head ? m1 : m0;
    float4 acc = make_float4(0.f, 0.f, 0.f, 0.f);
    float denom = 0.f;
    for (int i = s; i < e; i++) {
        int d = __ldg(&g_adj[i]);                       // broadcast
        float2 b = *(const float2*)(g_beta + 2 * d);    // broadcast
        float w = __expf((head ? b.y : b.x) - mh);
        float4 v = *(const float4*)(g_hlin + (size_t)d * 128 + (lane << 2));
        acc.x = fmaf(w, v.x, acc.x);
        acc.y = fmaf(w, v.y, acc.y);
        acc.z = fmaf(w, v.z, acc.z);
        acc.w = fmaf(w, v.w, acc.w);
        denom += w;
    }
    float inv = 1.f / (denom + 1e-16f);
    float deg = (float)(e - s);
    float4 hv = *(const float4*)(g_hlin + (size_t)n * 128 + (lane << 2));
    float4 r;
    r.x = fmaf(deg, hv.x, acc.x * inv);
    r.y = fmaf(deg, hv.y, acc.y * inv);
    r.z = fmaf(deg, hv.z, acc.z * inv);
    r.w = fmaf(deg, hv.w, acc.w * inv);
    float4 q;
    q.x = __shfl_xor_sync(0xffffffffu, r.x, 16);
    q.y = __shfl_xor_sync(0xffffffffu, r.y, 16);
    q.z = __shfl_xor_sync(0xffffffffu, r.z, 16);
    q.w = __shfl_xor_sync(0xffffffffu, r.w, 16);
    if (lane < 16) {
        int dl = lane << 2;
        float4 o4;
        o4.x = 0.5f * (r.x + q.x) + biases[64 + dl + 0];
        o4.y = 0.5f * (r.y + q.y) + biases[64 + dl + 1];
        o4.z = 0.5f * (r.z + q.z) + biases[64 + dl + 2];
        o4.w = 0.5f * (r.w + q.w) + biases[64 + dl + 3];
        *(float4*)(out + (size_t)n * 64 + dl) = o4;
    }
}

// ======================= launch =======================
extern "C" void kernel_launch(void* const* d_in, const int* in_sizes, int n_in,
                              void* d_out, int out_size) {
    const int* x = (const int*)d_in[0];
    const int* ei = (const int*)d_in[1];
    const float* emb = (const float*)d_in[2];
    const float* Ws = (const float*)d_in[3];
    const float* bs = (const float*)d_in[4];
    const float* atts = (const float*)d_in[5];
    const float* biases = (const float*)d_in[6];
    float* out = (float*)d_out;

    int n = in_sizes[0];
    int E = in_sizes[1] / 2;

    int nb = (n + 255) / 256;
    int eb = (E + 255) / 256;
    int wb = (n + 7) / 8;  // warp-per-node kernels, 8 warps/block

    k_init<<<nb, 256>>>(n);
    k_hist<<<eb, 256>>>(ei, E);
    k_scan<<<1, 1024>>>(n);
    k_scatter_init<<<nb, 256>>>(n);
    k_scatter<<<eb, 256>>>(ei, E);
    k_l0_prep<<<1, 256>>>(emb, Ws, bs, atts);
    k_l0_aggr<<<wb, 256>>>(x, biases, n);
    k_l1_gemm<<<wb, 256>>>(Ws, bs, atts, n);
    k_l1_aggr<<<wb, 256>>>(biases, out, n);
}